// round 8
// baseline (speedup 1.0000x reference)
#include <cuda_runtime.h>
#include <cstdint>
#include <cstddef>

#define BB 2
#define NN 100
#define HH 800
#define WW 1344
#define PP (HH*WW)            // 1075200 pixels per batch
#define WORDS (PP/32)         // 33600 words per plane
#define TILES (PP/128)        // 8400 tiles (1 tile = 128 pixels = 4 words)
#define Q4S (PP/4)            // 268800 uint4 chunks per plane
#define G 6                   // group size
#define NGP 17                // ceil(100/6) groups (ranks padded to 102)
#define NRANK (NGP*G)         // 102
#define HS 64                 // 2^G buckets
#define NSEM 134
#define TPB 256
#define WBLK 132              // 132*256 = 33792 >= WORDS

#define MASK_ELEMS (BB*NN*PP)
#define SEM_ELEMS  (BB*PP)

// ---------------- device state (scratch; re-derived every launch) ----------
__device__ uint32_t g_planes[BB][NRANK][WORDS]; // bitplanes by RANK (ballot layout)
__device__ int      g_order[BB][NN];
__device__ float    g_sscore[BB][NRANK];        // padded ranks get -1
__device__ int      g_scls[BB][NRANK];
__device__ int      g_area[BB][NRANK];
__device__ int      g_hist[BB][NGP][HS];
__device__ int      g_interA[BB][NGP][G];
__device__ unsigned g_ticket[BB][NGP+1];
__device__ int      g_flag[BB][NGP+1];
__device__ int      g_keptmask[BB][NGP];
__device__ int      g_nkept[BB];
__device__ int      g_kept_rank[BB][NN];
__device__ int      g_kept_val[BB][NN];
__device__ int      g_next_iid[BB];
__device__ int      g_cls_counts[BB][NSEM];
// transport flags
__device__ int      g_a_is_cls;
__device__ int      g_cls_f32;
__device__ int      g_sem_f32;
__device__ int      g_mask_byte;

// ---------------- init: zero all scratch (must rerun every replay) ---------
__global__ void k_init() {
    int idx = blockIdx.x * blockDim.x + threadIdx.x;
    int stride = gridDim.x * blockDim.x;
    int* h = &g_hist[0][0][0];
    for (int i = idx; i < BB*NGP*HS; i += stride) h[i] = 0;
    int* ia = &g_interA[0][0][0];
    for (int i = idx; i < BB*NGP*G; i += stride) ia[i] = 0;
    unsigned* tk = &g_ticket[0][0];
    int* fl = &g_flag[0][0];
    for (int i = idx; i < BB*(NGP+1); i += stride) { tk[i] = 0u; fl[i] = 0; }
    int* ar = &g_area[0][0];
    for (int i = idx; i < BB*NRANK; i += stride) ar[i] = 0;
    int* cc = &g_cls_counts[0][0];
    for (int i = idx; i < BB*NSEM; i += stride) cc[i] = 0;
    // pad ranks 100..101: score -1 (never kept), zero planes
    for (int i = idx; i < BB*(NRANK-NN); i += stride) {
        int b = i / (NRANK-NN), r = NN + i % (NRANK-NN);
        g_sscore[b][r] = -1.0f;
        g_scls[b][r] = 0;
    }
    for (int i = idx; i < BB*(NRANK-NN)*WORDS; i += stride) {
        int b = i / ((NRANK-NN)*WORDS);
        int rest = i % ((NRANK-NN)*WORDS);
        g_planes[b][NN + rest/WORDS][rest%WORDS] = 0u;
    }
    if (idx < BB) { g_nkept[idx] = 0; g_next_iid[idx] = 1; }
}

// ---------------- runtime transport classification --------------------------
__device__ __forceinline__ bool int_in(unsigned int raw, int lo, int hi) {
    int v = (int)raw; return v >= lo && v < hi;
}
__device__ __forceinline__ bool f32_in(unsigned int raw, int lo, int hi) {
    float f = __uint_as_float(raw);
    if (!(f >= (float)lo && f < (float)hi)) return false;
    return floorf(f) == f;
}

__global__ void k_detect(const unsigned int* __restrict__ pa,
                         const unsigned int* __restrict__ pb,
                         const unsigned int* __restrict__ sem,
                         const unsigned int* __restrict__ masks) {
    __shared__ int f_ai, f_af, f_bi, f_bf, f_si, f_sf, f_w;
    int t = threadIdx.x;
    if (t == 0) { f_ai=1; f_af=1; f_bi=1; f_bf=1; f_si=1; f_sf=1; f_w=1; }
    __syncthreads();
    if (t < BB*NN) {
        unsigned int va = pa[t], vb = pb[t];
        if (!int_in(va, 0, 80)) f_ai = 0;
        if (!f32_in(va, 0, 80)) f_af = 0;
        if (!int_in(vb, 0, 80)) f_bi = 0;
        if (!f32_in(vb, 0, 80)) f_bf = 0;
    }
    #pragma unroll
    for (int k = 0; k < 4; k++) {
        int i = (t + 256*k) * (SEM_ELEMS/1024);
        unsigned int v = sem[i];
        if (!int_in(v, 0, NSEM)) f_si = 0;
        if (!f32_in(v, 0, NSEM)) f_sf = 0;
    }
    #pragma unroll
    for (int k = 0; k < 4; k++) {
        unsigned int v = masks[t + 256*k];
        if (!(v == 0u || v == 1u || v == 0x3F800000u)) f_w = 0;
    }
    __syncthreads();
    if (t == 0) {
        int a_cls = (f_ai | f_af);
        g_a_is_cls = a_cls;
        g_cls_f32  = a_cls ? (f_af && !f_ai) : (f_bf && !f_bi);
        g_sem_f32  = (f_sf && !f_si);
        g_mask_byte = f_w ? 0 : 1;
    }
}

// ---------------- stable descending sort of 100 scores per batch -----------
__global__ void k_sort(const unsigned int* __restrict__ pa,
                       const unsigned int* __restrict__ pb) {
    const unsigned int* scores = g_a_is_cls ? pb : pa;
    const unsigned int* cls    = g_a_is_cls ? pa : pb;
    int clsf = g_cls_f32;
    __shared__ float ss[BB][NN];
    int t = threadIdx.x;
    for (int i = t; i < BB*NN; i += blockDim.x)
        ss[i/NN][i%NN] = __uint_as_float(scores[i]);
    __syncthreads();
    for (int idx = t; idx < BB*NN; idx += blockDim.x) {
        int b = idx / NN, i = idx % NN;
        float si = ss[b][i];
        int r = 0;
        #pragma unroll 4
        for (int j = 0; j < NN; j++) {
            float sj = ss[b][j];
            r += (sj > si) || (sj == si && j < i);
        }
        unsigned int rawc = cls[b*NN + i];
        int c = clsf ? (int)__uint_as_float(rawc) : (int)rawc;
        g_order[b][r]  = i;
        g_sscore[b][r] = si;
        g_scls[b][r]   = c;
    }
}

// ---------------- pack masks into bitplanes (ballot layout) ------------------
// Layout: word w = tile*4 + k; bit `lane` of word = pixel tile*128 + lane*4 + k.
__global__ void k_pack(const unsigned int* __restrict__ masks) {
    int b = blockIdx.z, r = blockIdx.y;
    int t = threadIdx.x, lane = t & 31, warp = t >> 5;
    bool cand = (g_sscore[b][r] >= 0.5f);
    int orig = g_order[b][r];
    int T0 = blockIdx.x * 64 + warp * 8;
    int myarea = 0;

    if (!g_mask_byte) {
        const uint4* mp = (const uint4*)(masks + (size_t)(b*NN + orig) * PP);
        #pragma unroll
        for (int j = 0; j < 8; j++) {
            int T = T0 + j;
            if (T < TILES) {
                uint4 x = make_uint4(0u,0u,0u,0u);
                if (cand) x = mp[T*32 + lane];
                uint32_t b0 = __ballot_sync(0xffffffffu, x.x != 0u);
                uint32_t b1 = __ballot_sync(0xffffffffu, x.y != 0u);
                uint32_t b2 = __ballot_sync(0xffffffffu, x.z != 0u);
                uint32_t b3 = __ballot_sync(0xffffffffu, x.w != 0u);
                if (lane == 0) {
                    *(uint4*)&g_planes[b][r][T*4] = make_uint4(b0,b1,b2,b3);
                    myarea += __popc(b0)+__popc(b1)+__popc(b2)+__popc(b3);
                }
            }
        }
    } else {
        // byte-packed bool fallback: lane loads 4 bytes (4 pixels)
        const unsigned int* mp = (const unsigned int*)((const unsigned char*)masks
                                   + (size_t)(b*NN + orig) * PP);
        #pragma unroll
        for (int j = 0; j < 8; j++) {
            int T = T0 + j;
            if (T < TILES) {
                unsigned int x = cand ? mp[T*32 + lane] : 0u;
                uint32_t b0 = __ballot_sync(0xffffffffu, (x & 0x000000FFu) != 0u);
                uint32_t b1 = __ballot_sync(0xffffffffu, (x & 0x0000FF00u) != 0u);
                uint32_t b2 = __ballot_sync(0xffffffffu, (x & 0x00FF0000u) != 0u);
                uint32_t b3 = __ballot_sync(0xffffffffu, (x & 0xFF000000u) != 0u);
                if (lane == 0) {
                    *(uint4*)&g_planes[b][r][T*4] = make_uint4(b0,b1,b2,b3);
                    myarea += __popc(b0)+__popc(b1)+__popc(b2)+__popc(b3);
                }
            }
        }
    }
    __shared__ int sa[TPB/32];
    if (lane == 0) sa[warp] = myarea;
    __syncthreads();
    if (t == 0) {
        int s = 0;
        #pragma unroll
        for (int k = 0; k < TPB/32; k++) s += sa[k];
        if (s) atomicAdd(&g_area[b][r], s);
    }
}

// ---------------- fused: 17 phases + stuff hist + final write ---------------
__global__ void __launch_bounds__(TPB, 4)
k_fused(const unsigned int* __restrict__ sem, uint4* __restrict__ out) {
    int b = blockIdx.y;
    int t = threadIdx.x, lane = t & 31, warp = t >> 5;
    int w = blockIdx.x * TPB + t;
    bool valid = (w < WORDS);
    uint32_t c = 0;                 // claimed word (register-resident)
    __shared__ int s_km;
    __shared__ unsigned s_old;
    __shared__ uint32_t s_cl[TPB];
    __shared__ int s_cnt[NSEM];
    __shared__ int s_nk;
    __shared__ int s_kr[NN];
    __shared__ int s_kv[NN];

    // ================= phases =================
    for (int g = 0; g < NGP; g++) {
        uint32_t pw[G];
        #pragma unroll
        for (int i = 0; i < G; i++) pw[i] = valid ? g_planes[b][g*G+i][w] : 0u;

        // interA: |m_i & claimed-before-group|
        #pragma unroll
        for (int i = 0; i < G; i++) {
            int s = __reduce_add_sync(0xffffffffu, __popc(pw[i] & c));
            if (lane == i && s) atomicAdd(&g_interA[b][g][i], s);
        }

        // bucket counts via enumeration (no per-pixel atomics)
        uint32_t u = valid ? ~c : 0u;
        int acc0 = 0, acc1 = 0;
        if (__any_sync(0xffffffffu, u != 0u)) {
            #pragma unroll
            for (int v = 0; v < HS; v++) {
                uint32_t m = u;
                m &= (v & 1)  ? pw[0] : ~pw[0];
                m &= (v & 2)  ? pw[1] : ~pw[1];
                m &= (v & 4)  ? pw[2] : ~pw[2];
                m &= (v & 8)  ? pw[3] : ~pw[3];
                m &= (v & 16) ? pw[4] : ~pw[4];
                m &= (v & 32) ? pw[5] : ~pw[5];
                int s = __reduce_add_sync(0xffffffffu, __popc(m));
                if (lane == (v & 31)) { if (v < 32) acc0 = s; else acc1 = s; }
            }
            if (acc0) atomicAdd(&g_hist[b][g][lane], acc0);
            if (acc1) atomicAdd(&g_hist[b][g][32+lane], acc1);
        }

        // barrier: ticket + last-block decision + flag
        __threadfence();
        __syncthreads();
        if (t == 0) s_old = atomicAdd(&g_ticket[b][g], 1u);
        __syncthreads();
        if (s_old == gridDim.x - 1) {
            if (warp == 0) {
                int h0 = __ldcg(&g_hist[b][g][lane]);
                int h1 = __ldcg(&g_hist[b][g][32+lane]);
                int keptm = 0;
                int iid = __ldcg(&g_next_iid[b]);
                int nk  = __ldcg(&g_nkept[b]);
                int p0 = lane, p1 = 32 + lane;
                for (int i = 0; i < G; i++) {
                    int r = g*G + i;
                    float sc = g_sscore[b][r];
                    int area  = __ldcg(&g_area[b][r]);
                    int inter = __ldcg(&g_interA[b][g][i]);
                    int loc = 0;
                    if (((p0 >> i) & 1) && (p0 & keptm)) loc += h0;
                    if (((p1 >> i) & 1) && (p1 & keptm)) loc += h1;
                    inter += __reduce_add_sync(0xffffffffu, loc);
                    bool keep = (sc >= 0.5f) && (area > 0) &&
                                ((float)inter <= 0.5f * (float)area);
                    if (keep) {
                        if (lane == 0) {
                            g_kept_rank[b][nk] = r;
                            g_kept_val[b][nk]  = g_scls[b][r] + iid * 1000;
                        }
                        keptm |= 1 << i;
                        iid++; nk++;
                    }
                }
                if (lane == 0) {
                    g_keptmask[b][g] = keptm;
                    g_next_iid[b] = iid;
                    g_nkept[b] = nk;
                    __threadfence();
                    atomicExch(&g_flag[b][g], 1);
                }
            }
            __syncthreads();
        }
        if (t == 0) {
            while (__ldcg(&g_flag[b][g]) == 0) __nanosleep(64);
            __threadfence();
            s_km = __ldcg(&g_keptmask[b][g]);
        }
        __syncthreads();
        int km = s_km;
        #pragma unroll
        for (int i = 0; i < G; i++)
            if ((km >> i) & 1) c |= pw[i];
        __syncthreads();
    }

    // ================= stuff histogram =================
    if (!valid) c = 0xFFFFFFFFu;     // OOB: fully claimed -> no contribution
    s_cl[t] = c;
    for (int i = t; i < NSEM; i += TPB) s_cnt[i] = 0;
    __syncthreads();

    int semf = g_sem_f32;
    const uint4* sp4 = (const uint4*)(sem + (size_t)b * PP);
    #pragma unroll
    for (int j = 0; j < 8; j++) {
        int tl = warp*8 + j;                  // local tile
        int T = blockIdx.x*64 + tl;           // global tile
        if (T < TILES) {
            uint32_t nibc = ((s_cl[tl*4+0] >> lane) & 1u)
                          | (((s_cl[tl*4+1] >> lane) & 1u) << 1)
                          | (((s_cl[tl*4+2] >> lane) & 1u) << 2)
                          | (((s_cl[tl*4+3] >> lane) & 1u) << 3);
            if (nibc != 0xFu) {
                uint4 x = sp4[T*32 + lane];
                unsigned int vv[4] = {x.x, x.y, x.z, x.w};
                #pragma unroll
                for (int k = 0; k < 4; k++) {
                    if (!((nibc >> k) & 1u)) {
                        int s = semf ? (int)__uint_as_float(vv[k]) : (int)vv[k];
                        if (s >= 0 && s < NSEM) atomicAdd(&s_cnt[s], 1);
                    }
                }
            }
        }
    }
    __syncthreads();
    for (int i = t; i < NSEM; i += TPB)
        if (s_cnt[i]) atomicAdd(&g_cls_counts[b][i], s_cnt[i]);

    // barrier for counts
    __threadfence();
    __syncthreads();
    if (t == 0) s_old = atomicAdd(&g_ticket[b][NGP], 1u);
    __syncthreads();
    if (s_old == gridDim.x - 1) {
        if (t == 0) { __threadfence(); atomicExch(&g_flag[b][NGP], 1); }
        __syncthreads();
    }
    if (t == 0) {
        while (__ldcg(&g_flag[b][NGP]) == 0) __nanosleep(64);
        __threadfence();
        s_nk = __ldcg(&g_nkept[b]);
    }
    __syncthreads();
    int nk = s_nk;
    for (int i = t; i < NSEM; i += TPB) s_cnt[i] = __ldcg(&g_cls_counts[b][i]);
    for (int i = t; i < nk; i += TPB) {
        s_kr[i] = __ldcg(&g_kept_rank[b][i]);
        s_kv[i] = __ldcg(&g_kept_val[b][i]);
    }
    __syncthreads();

    // ================= final write (float-encoded output) =================
    uint4* op4 = out + (size_t)b * Q4S;
    #pragma unroll
    for (int j = 0; j < 8; j++) {
        int tl = warp*8 + j;
        int T = blockIdx.x*64 + tl;
        if (T < TILES) {
            uint32_t nibc = ((s_cl[tl*4+0] >> lane) & 1u)
                          | (((s_cl[tl*4+1] >> lane) & 1u) << 1)
                          | (((s_cl[tl*4+2] >> lane) & 1u) << 2)
                          | (((s_cl[tl*4+3] >> lane) & 1u) << 3);
            unsigned int vals[4];
            uint32_t rem = nibc;
            for (int k = 0; k < nk && rem; k++) {
                int rk = s_kr[k];
                uint32_t pm = 0;
                #pragma unroll
                for (int kk = 0; kk < 4; kk++)
                    if ((rem >> kk) & 1u)
                        pm |= ((g_planes[b][rk][T*4+kk] >> lane) & 1u) << kk;
                if (pm) {
                    unsigned int fv = (unsigned int)__float_as_int((float)s_kv[k]);
                    rem ^= pm;
                    while (pm) { int p = __ffs(pm) - 1; pm &= pm - 1; vals[p] = fv; }
                }
            }
            uint32_t un = (~nibc) & 0xFu;
            if (un) {
                uint4 x = sp4[T*32 + lane];
                unsigned int vv[4] = {x.x, x.y, x.z, x.w};
                while (un) {
                    int p = __ffs(un) - 1; un &= un - 1;
                    int s = semf ? (int)__uint_as_float(vv[p]) : (int)vv[p];
                    int v = (s >= 0 && s < NSEM-1 && s_cnt[s] >= 4096) ? (s + 80) : 0;
                    vals[p] = (unsigned int)__float_as_int((float)v);
                }
            }
            op4[T*32 + lane] = make_uint4(vals[0], vals[1], vals[2], vals[3]);
        }
    }
}

// ---------------- launch -----------------------------------------------------
extern "C" void kernel_launch(void* const* d_in, const int* in_sizes, int n_in,
                              void* d_out, int out_size) {
    const void* masks = nullptr;
    const void* sem   = nullptr;
    const void* smallA = nullptr;
    const void* smallB = nullptr;
    for (int i = 0; i < n_in; i++) {
        if (in_sizes[i] == MASK_ELEMS)      masks = d_in[i];
        else if (in_sizes[i] == SEM_ELEMS)  sem   = d_in[i];
        else if (in_sizes[i] == BB*NN) {
            if (!smallA) smallA = d_in[i]; else smallB = d_in[i];
        }
    }
    if (!masks)  masks  = d_in[0];
    if (!smallA) smallA = d_in[1];
    if (!smallB) smallB = d_in[2];
    if (!sem)    sem    = d_in[3];

    k_init<<<256, 256>>>();
    k_detect<<<1, 256>>>((const unsigned int*)smallA, (const unsigned int*)smallB,
                         (const unsigned int*)sem, (const unsigned int*)masks);
    k_sort<<<1, 256>>>((const unsigned int*)smallA, (const unsigned int*)smallB);
    k_pack<<<dim3(WBLK, NN, BB), TPB>>>((const unsigned int*)masks);
    k_fused<<<dim3(WBLK, BB), TPB>>>((const unsigned int*)sem, (uint4*)d_out);
}

// round 9
// speedup vs baseline: 1.2453x; 1.2453x over previous
#include <cuda_runtime.h>
#include <cstdint>
#include <cstddef>

#define BB 2
#define NN 100
#define HH 800
#define WW 1344
#define PP (HH*WW)          // 1075200 pixels per batch
#define WORDS (PP/32)       // 33600 words per plane
#define Q4S (PP/4)          // 268800 uint4 chunks per plane
#define G 10                // group size
#define NG (NN/G)           // 10 groups
#define HSIZE (1<<G)        // 1024 histogram buckets
#define NSEM 134
#define TPB 256
#define WBLK ((WORDS + TPB - 1)/TPB)   // 132

#define MASK_ELEMS (BB*NN*PP)
#define SEM_ELEMS  (BB*PP)

// ---------------- device state (scratch; re-derived every launch) ----------
__device__ uint32_t g_planes[BB][NN][WORDS];   // bitplanes, linear layout: word w bit b = pixel 32w+b
__device__ uint32_t g_claimed[BB][WORDS];
__device__ int      g_order[BB][NN];
__device__ float    g_sscore[BB][NN];
__device__ int      g_scls[BB][NN];
__device__ int      g_area[BB][NN];
__device__ int      g_hist[BB][NG][HSIZE];
__device__ int      g_interA[BB][NG][G];
__device__ unsigned g_ticket[BB][NG];
__device__ int      g_keptmask[BB][NG];
__device__ int      g_nkept[BB];
__device__ int      g_kept_rank[BB][NN];
__device__ int      g_kept_val[BB][NN];
__device__ int      g_next_iid[BB];
__device__ int      g_cls_counts[BB][NSEM];
// transport flags
__device__ int      g_a_is_cls;
__device__ int      g_cls_f32;
__device__ int      g_sem_f32;
__device__ int      g_mask_byte;

// ---------------- init -------------------------------------------------------
__global__ void k_init() {
    int idx = blockIdx.x * blockDim.x + threadIdx.x;
    int stride = gridDim.x * blockDim.x;
    uint32_t* cl = &g_claimed[0][0];
    for (int i = idx; i < BB*WORDS; i += stride) cl[i] = 0u;
    int* h = &g_hist[0][0][0];
    for (int i = idx; i < BB*NG*HSIZE; i += stride) h[i] = 0;
    int* ia = &g_interA[0][0][0];
    for (int i = idx; i < BB*NG*G; i += stride) ia[i] = 0;
    unsigned* tk = &g_ticket[0][0];
    int* km = &g_keptmask[0][0];
    for (int i = idx; i < BB*NG; i += stride) { tk[i] = 0u; km[i] = 0; }
    int* ar = &g_area[0][0];
    for (int i = idx; i < BB*NN; i += stride) ar[i] = 0;
    int* cc = &g_cls_counts[0][0];
    for (int i = idx; i < BB*NSEM; i += stride) cc[i] = 0;
    if (idx < BB) { g_nkept[idx] = 0; g_next_iid[idx] = 1; }
}

// ---------------- runtime transport classification --------------------------
__device__ __forceinline__ bool int_in(unsigned int raw, int lo, int hi) {
    int v = (int)raw; return v >= lo && v < hi;
}
__device__ __forceinline__ bool f32_in(unsigned int raw, int lo, int hi) {
    float f = __uint_as_float(raw);
    if (!(f >= (float)lo && f < (float)hi)) return false;
    return floorf(f) == f;
}

__global__ void k_detect(const unsigned int* __restrict__ pa,
                         const unsigned int* __restrict__ pb,
                         const unsigned int* __restrict__ sem,
                         const unsigned int* __restrict__ masks) {
    __shared__ int f_ai, f_af, f_bi, f_bf, f_si, f_sf, f_w;
    int t = threadIdx.x;
    if (t == 0) { f_ai=1; f_af=1; f_bi=1; f_bf=1; f_si=1; f_sf=1; f_w=1; }
    __syncthreads();
    if (t < BB*NN) {
        unsigned int va = pa[t], vb = pb[t];
        if (!int_in(va, 0, 80)) f_ai = 0;
        if (!f32_in(va, 0, 80)) f_af = 0;
        if (!int_in(vb, 0, 80)) f_bi = 0;
        if (!f32_in(vb, 0, 80)) f_bf = 0;
    }
    #pragma unroll
    for (int k = 0; k < 4; k++) {
        int i = (t + 256*k) * (SEM_ELEMS/1024);
        unsigned int v = sem[i];
        if (!int_in(v, 0, NSEM)) f_si = 0;
        if (!f32_in(v, 0, NSEM)) f_sf = 0;
    }
    #pragma unroll
    for (int k = 0; k < 4; k++) {
        unsigned int v = masks[t + 256*k];
        if (!(v == 0u || v == 1u || v == 0x3F800000u)) f_w = 0;
    }
    __syncthreads();
    if (t == 0) {
        int a_cls = (f_ai | f_af);
        g_a_is_cls = a_cls;
        g_cls_f32  = a_cls ? (f_af && !f_ai) : (f_bf && !f_bi);
        g_sem_f32  = (f_sf && !f_si);
        g_mask_byte = f_w ? 0 : 1;
    }
}

// ---------------- stable descending sort of 100 scores per batch -----------
__global__ void k_sort(const unsigned int* __restrict__ pa,
                       const unsigned int* __restrict__ pb) {
    const unsigned int* scores = g_a_is_cls ? pb : pa;
    const unsigned int* cls    = g_a_is_cls ? pa : pb;
    int clsf = g_cls_f32;
    __shared__ float ss[BB][NN];
    int t = threadIdx.x;
    for (int i = t; i < BB*NN; i += blockDim.x)
        ss[i/NN][i%NN] = __uint_as_float(scores[i]);
    __syncthreads();
    for (int idx = t; idx < BB*NN; idx += blockDim.x) {
        int b = idx / NN, i = idx % NN;
        float si = ss[b][i];
        int r = 0;
        #pragma unroll 4
        for (int j = 0; j < NN; j++) {
            float sj = ss[b][j];
            r += (sj > si) || (sj == si && j < i);
        }
        unsigned int rawc = cls[b*NN + i];
        int c = clsf ? (int)__uint_as_float(rawc) : (int)rawc;
        g_order[b][r]  = i;
        g_sscore[b][r] = si;
        g_scls[b][r]   = c;
    }
}

// ---------------- pack masks into bitplanes + areas --------------------------
__global__ void k_pack(const unsigned int* __restrict__ masks) {
    int b = blockIdx.z, r = blockIdx.y;
    int t = threadIdx.x;
    int lane = t & 31, warp = t >> 5;
    bool cand = (g_sscore[b][r] >= 0.5f);
    int orig = g_order[b][r];
    int wbase = blockIdx.x * 256;
    int myarea = 0;

    if (!g_mask_byte) {
        const uint4* mp = (const uint4*)(masks + (size_t)(b*NN + orig) * PP);
        int sub = lane & 7;
        #pragma unroll
        for (int j = 0; j < 8; j++) {
            int q = (wbase + warp*32)*8 + j*32 + lane;   // uint4 index, coalesced
            uint32_t nib = 0;
            if (cand && q < Q4S) {
                uint4 x = __ldcs(&mp[q]);                // streaming: don't pollute L2
                nib  = (uint32_t)(x.x != 0u);
                nib |= (uint32_t)(x.y != 0u) << 1;
                nib |= (uint32_t)(x.z != 0u) << 2;
                nib |= (uint32_t)(x.w != 0u) << 3;
            }
            myarea += __popc(nib);
            uint32_t v = nib << (4*sub);
            v |= __shfl_xor_sync(0xffffffffu, v, 1);
            v |= __shfl_xor_sync(0xffffffffu, v, 2);
            v |= __shfl_xor_sync(0xffffffffu, v, 4);
            int w = wbase + warp*32 + j*4 + (lane >> 3);
            if (sub == 0 && w < WORDS) g_planes[b][r][w] = v;
        }
    } else {
        int w = wbase + t;
        uint32_t bits = 0;
        if (w < WORDS && cand) {
            const uint4* q = (const uint4*)((const unsigned char*)masks
                              + (size_t)(b*NN + orig)*PP + (size_t)w*32);
            uint4 x = __ldcs(&q[0]), y = __ldcs(&q[1]);
            uint32_t v[8] = {x.x, x.y, x.z, x.w, y.x, y.y, y.z, y.w};
            #pragma unroll
            for (int j = 0; j < 8; j++) {
                uint32_t nv = (v[j] | (v[j] >> 7) | (v[j] >> 14) | (v[j] >> 21)) & 0xFu;
                bits |= nv << (4*j);
            }
        }
        if (w < WORDS) g_planes[b][r][w] = bits;
        myarea = __popc(bits);
    }

    #pragma unroll
    for (int o = 16; o; o >>= 1) myarea += __shfl_down_sync(0xffffffffu, myarea, o);
    __shared__ int sa[TPB/32];
    if (lane == 0) sa[warp] = myarea;
    __syncthreads();
    if (t == 0) {
        int s = 0;
        #pragma unroll
        for (int k = 0; k < TPB/32; k++) s += sa[k];
        if (s) atomicAdd(&g_area[b][r], s);
    }
}

// ---------------- per-group phase ------------------------------------------
// Dead-group cutoff: ranks sorted descending => if sscore[g*G] < 0.5 the whole
// group can never keep anything; skip hist/decisions. If additionally the
// previous group kept nothing, exit immediately.
__global__ void k_phase(int g) {
    int b = blockIdx.y;
    int t = threadIdx.x;
    int lane = t & 31, warp = t >> 5;
    int w = blockIdx.x * TPB + t;

    bool live = (g_sscore[b][g*G] >= 0.5f);
    int kmprev = (g > 0) ? g_keptmask[b][g-1] : 0;
    if (!live && kmprev == 0) return;           // nothing to do for this group

    // claimed update from previous group's kept masks
    uint32_t c = 0;
    if (w < WORDS) {
        c = g_claimed[b][w];
        if (kmprev) {
            int km = kmprev;
            int pbase = (g-1)*G;
            while (km) { int i = __ffs(km) - 1; km &= km - 1; c |= g_planes[b][pbase+i][w]; }
            g_claimed[b][w] = c;
        }
    }
    if (!live) return;                          // no candidates in this group

    __shared__ int s_hist[TPB/32][HSIZE];       // per-warp histograms (32KB)
    __shared__ int s_a[G];
    __shared__ unsigned s_old;
    for (int i = t; i < (TPB/32)*HSIZE; i += TPB) (&s_hist[0][0])[i] = 0;
    if (t < G) s_a[t] = 0;
    __syncthreads();

    int a_loc[G];
    #pragma unroll
    for (int i = 0; i < G; i++) a_loc[i] = 0;

    if (w < WORDS) {
        int base = g*G;
        uint32_t pw[G];
        #pragma unroll
        for (int i = 0; i < G; i++) pw[i] = g_planes[b][base+i][w];
        #pragma unroll
        for (int i = 0; i < G; i++) a_loc[i] = __popc(pw[i] & c);
        uint32_t u = ~c;
        while (u) {
            int p = __ffs(u) - 1; u &= u - 1;
            int pat = 0;
            #pragma unroll
            for (int i = 0; i < G; i++) pat |= (int)((pw[i] >> p) & 1u) << i;
            atomicAdd(&s_hist[warp][pat], 1);
        }
    }
    #pragma unroll
    for (int i = 0; i < G; i++) {
        int v = a_loc[i];
        #pragma unroll
        for (int o = 16; o; o >>= 1) v += __shfl_down_sync(0xffffffffu, v, o);
        if (lane == 0 && v) atomicAdd(&s_a[i], v);
    }
    __syncthreads();
    for (int i = t; i < HSIZE; i += TPB) {
        int s = 0;
        #pragma unroll
        for (int k = 0; k < TPB/32; k++) s += s_hist[k][i];
        if (s) atomicAdd(&g_hist[b][g][i], s);
    }
    if (t < G && s_a[t]) atomicAdd(&g_interA[b][g][t], s_a[t]);
    __syncthreads();
    if (t == 0) {
        __threadfence();
        s_old = atomicAdd(&g_ticket[b][g], 1u);
    }
    __syncthreads();
    if (s_old != gridDim.x - 1) return;

    if (t >= 32) return;
    const int HL = HSIZE/32;
    int h[HL];
    #pragma unroll
    for (int k = 0; k < HL; k++) h[k] = __ldcg(&g_hist[b][g][lane*HL + k]);
    int keptm = 0;
    int iid = g_next_iid[b];
    int nk  = g_nkept[b];
    int base = g*G;
    for (int i = 0; i < G; i++) {
        int r = base + i;
        float s  = g_sscore[b][r];
        int area = __ldcg(&g_area[b][r]);
        int inter = __ldcg(&g_interA[b][g][i]);
        int loc = 0;
        #pragma unroll
        for (int k = 0; k < HL; k++) {
            int pat = lane*HL + k;
            if (((pat >> i) & 1) && (pat & keptm)) loc += h[k];
        }
        #pragma unroll
        for (int o = 16; o; o >>= 1) loc += __shfl_xor_sync(0xffffffffu, loc, o);
        inter += loc;
        bool keep = (s >= 0.5f) && (area > 0) && ((float)inter <= 0.5f * (float)area);
        if (keep) {
            if (lane == 0) {
                g_kept_rank[b][nk] = r;
                g_kept_val[b][nk]  = g_scls[b][r] + iid * 1000;
            }
            keptm |= 1 << i;
            iid++; nk++;
        }
    }
    if (lane == 0) {
        g_keptmask[b][g] = keptm;
        g_next_iid[b] = iid;
        g_nkept[b] = nk;
    }
}

// ---------------- stuff class histogram over unclaimed pixels ---------------
__global__ void k_stuff_hist(const unsigned int* __restrict__ sem) {
    int b = blockIdx.y;
    int t = threadIdx.x;
    int lane = t & 31, warp = t >> 5;
    int semf = g_sem_f32;
    __shared__ uint32_t s_cl[TPB];
    __shared__ int s_cnt[NSEM];
    int w = blockIdx.x * TPB + t;
    uint32_t c = 0xFFFFFFFFu;
    if (w < WORDS) {
        c = g_claimed[b][w];
        int km = g_keptmask[b][NG-1];
        int pbase = (NG-1)*G;
        while (km) { int i = __ffs(km) - 1; km &= km - 1; c |= g_planes[b][pbase+i][w]; }
        g_claimed[b][w] = c;   // final claimed
    }
    s_cl[t] = c;
    for (int i = t; i < NSEM; i += TPB) s_cnt[i] = 0;
    __syncthreads();

    const uint4* sp4 = (const uint4*)(sem + (size_t)b*PP);
    int wbase = blockIdx.x * 256;
    #pragma unroll
    for (int j = 0; j < 8; j++) {
        int q = (wbase + warp*32)*8 + j*32 + lane;
        if (q < Q4S) {
            int lwi = warp*32 + j*4 + (lane >> 3);
            uint32_t nibc = (s_cl[lwi] >> (4*(lane & 7))) & 0xFu;
            if (nibc != 0xFu) {
                uint4 x = sp4[q];
                unsigned int vv[4] = {x.x, x.y, x.z, x.w};
                #pragma unroll
                for (int k = 0; k < 4; k++) {
                    if (!((nibc >> k) & 1u)) {
                        int s = semf ? (int)__uint_as_float(vv[k]) : (int)vv[k];
                        if (s >= 0 && s < NSEM) atomicAdd(&s_cnt[s], 1);
                    }
                }
            }
        }
    }
    __syncthreads();
    for (int i = t; i < NSEM; i += TPB)
        if (s_cnt[i]) atomicAdd(&g_cls_counts[b][i], s_cnt[i]);
}

// ---------------- final output write (float32-encoded) ----------------------
__global__ void k_final(const unsigned int* __restrict__ sem, uint4* __restrict__ out) {
    int b = blockIdx.y;
    int t = threadIdx.x;
    int lane = t & 31, warp = t >> 5;
    int semf = g_sem_f32;
    __shared__ uint32_t s_cl[TPB];
    __shared__ int s_kval[NN];
    __shared__ int s_krank[NN];
    int w = blockIdx.x * TPB + t;
    s_cl[t] = (w < WORDS) ? g_claimed[b][w] : 0u;
    int nk = g_nkept[b];
    if (t < nk) { s_kval[t] = g_kept_val[b][t]; s_krank[t] = g_kept_rank[b][t]; }
    __syncthreads();

    const uint4* sp4 = (const uint4*)(sem + (size_t)b*PP);
    uint4* op4 = out + (size_t)b*Q4S;
    int wbase = blockIdx.x * 256;
    #pragma unroll
    for (int j = 0; j < 8; j++) {
        int q = (wbase + warp*32)*8 + j*32 + lane;
        if (q < Q4S) {
            int lwi = warp*32 + j*4 + (lane >> 3);
            int w2 = wbase + lwi;
            int nsh = 4*(lane & 7);
            uint32_t nibc = (s_cl[lwi] >> nsh) & 0xFu;
            unsigned int vals[4];
            uint32_t rem = nibc;
            for (int k = 0; k < nk && rem; k++) {
                uint32_t pm = ((g_planes[b][s_krank[k]][w2] >> nsh) & 0xFu) & rem;
                if (pm) {
                    unsigned int fv = (unsigned int)__float_as_int((float)s_kval[k]);
                    rem ^= pm;
                    while (pm) { int p = __ffs(pm) - 1; pm &= pm - 1; vals[p] = fv; }
                }
            }
            uint32_t un = (~nibc) & 0xFu;
            if (un) {
                uint4 x = sp4[q];
                unsigned int vv[4] = {x.x, x.y, x.z, x.w};
                while (un) {
                    int p = __ffs(un) - 1; un &= un - 1;
                    int s = semf ? (int)__uint_as_float(vv[p]) : (int)vv[p];
                    int v = (s >= 0 && s < NSEM-1 && g_cls_counts[b][s] >= 4096) ? (s + 80) : 0;
                    vals[p] = (unsigned int)__float_as_int((float)v);
                }
            }
            op4[q] = make_uint4(vals[0], vals[1], vals[2], vals[3]);
        }
    }
}

// ---------------- launch -----------------------------------------------------
extern "C" void kernel_launch(void* const* d_in, const int* in_sizes, int n_in,
                              void* d_out, int out_size) {
    const void* masks = nullptr;
    const void* sem   = nullptr;
    const void* smallA = nullptr;
    const void* smallB = nullptr;
    for (int i = 0; i < n_in; i++) {
        if (in_sizes[i] == MASK_ELEMS)      masks = d_in[i];
        else if (in_sizes[i] == SEM_ELEMS)  sem   = d_in[i];
        else if (in_sizes[i] == BB*NN) {
            if (!smallA) smallA = d_in[i]; else smallB = d_in[i];
        }
    }
    if (!masks)  masks  = d_in[0];
    if (!smallA) smallA = d_in[1];
    if (!smallB) smallB = d_in[2];
    if (!sem)    sem    = d_in[3];

    k_init<<<256, 256>>>();
    k_detect<<<1, 256>>>((const unsigned int*)smallA, (const unsigned int*)smallB,
                         (const unsigned int*)sem, (const unsigned int*)masks);
    k_sort<<<1, 256>>>((const unsigned int*)smallA, (const unsigned int*)smallB);
    k_pack<<<dim3(WBLK, NN, BB), TPB>>>((const unsigned int*)masks);
    for (int g = 0; g < NG; g++)
        k_phase<<<dim3(WBLK, BB), TPB>>>(g);
    k_stuff_hist<<<dim3(WBLK, BB), TPB>>>((const unsigned int*)sem);
    k_final<<<dim3(WBLK, BB), TPB>>>((const unsigned int*)sem, (uint4*)d_out);
}

// round 10
// speedup vs baseline: 1.4171x; 1.1380x over previous
#include <cuda_runtime.h>
#include <cstdint>
#include <cstddef>

#define BB 2
#define NN 100
#define HH 800
#define WW 1344
#define PP (HH*WW)          // 1075200 pixels per batch
#define WORDS (PP/32)       // 33600 words per plane
#define Q4S (PP/4)          // 268800 uint4 chunks per plane
#define G 10                // group size
#define NG (NN/G)           // 10 groups
#define HSIZE (1<<G)        // 1024 histogram buckets
#define NSEM 134
#define TPB 256
#define WBLK ((WORDS + TPB - 1)/TPB)   // 132

#define MASK_ELEMS (BB*NN*PP)
#define SEM_ELEMS  (BB*PP)

// Bit layout (permuted, consistent across ALL kernels):
//   word w = B*256 + wp*32 + lane   (B=block, wp=warp, lane)
//   bit (4j+k) of word w  <->  component k of uint4 q = B*2048 + wp*256 + j*32 + lane

// ---------------- device state ----------------------------------------------
__device__ uint32_t g_planes[BB][NN][WORDS];
__device__ uint32_t g_claimed[BB][WORDS];
__device__ int      g_order[BB][NN];
__device__ float    g_sscore[BB][NN];
__device__ int      g_scls[BB][NN];
__device__ int      g_area[BB][NN];
__device__ int      g_hist[BB][NG][HSIZE];
__device__ int      g_interA[BB][NG][G];
__device__ unsigned g_ticket[BB][NG];
__device__ int      g_keptmask[BB][NG];
__device__ int      g_nkept[BB];
__device__ int      g_kept_rank[BB][NN];
__device__ int      g_kept_val[BB][NN];
__device__ int      g_next_iid[BB];
__device__ int      g_cls_counts[BB][NSEM];
// transport flags
__device__ int      g_a_is_cls;
__device__ int      g_cls_f32;
__device__ int      g_sem_f32;
__device__ int      g_mask_byte;

// ---------------- init -------------------------------------------------------
__global__ void k_init() {
    int idx = blockIdx.x * blockDim.x + threadIdx.x;
    int stride = gridDim.x * blockDim.x;
    uint32_t* cl = &g_claimed[0][0];
    for (int i = idx; i < BB*WORDS; i += stride) cl[i] = 0u;
    int* h = &g_hist[0][0][0];
    for (int i = idx; i < BB*NG*HSIZE; i += stride) h[i] = 0;
    int* ia = &g_interA[0][0][0];
    for (int i = idx; i < BB*NG*G; i += stride) ia[i] = 0;
    unsigned* tk = &g_ticket[0][0];
    int* km = &g_keptmask[0][0];
    for (int i = idx; i < BB*NG; i += stride) { tk[i] = 0u; km[i] = 0; }
    int* ar = &g_area[0][0];
    for (int i = idx; i < BB*NN; i += stride) ar[i] = 0;
    int* cc = &g_cls_counts[0][0];
    for (int i = idx; i < BB*NSEM; i += stride) cc[i] = 0;
    if (idx < BB) { g_nkept[idx] = 0; g_next_iid[idx] = 1; }
}

// ---------------- runtime transport classification --------------------------
__device__ __forceinline__ bool int_in(unsigned int raw, int lo, int hi) {
    int v = (int)raw; return v >= lo && v < hi;
}
__device__ __forceinline__ bool f32_in(unsigned int raw, int lo, int hi) {
    float f = __uint_as_float(raw);
    if (!(f >= (float)lo && f < (float)hi)) return false;
    return floorf(f) == f;
}

__global__ void k_detect(const unsigned int* __restrict__ pa,
                         const unsigned int* __restrict__ pb,
                         const unsigned int* __restrict__ sem,
                         const unsigned int* __restrict__ masks) {
    __shared__ int f_ai, f_af, f_bi, f_bf, f_si, f_sf, f_w;
    int t = threadIdx.x;
    if (t == 0) { f_ai=1; f_af=1; f_bi=1; f_bf=1; f_si=1; f_sf=1; f_w=1; }
    __syncthreads();
    if (t < BB*NN) {
        unsigned int va = pa[t], vb = pb[t];
        if (!int_in(va, 0, 80)) f_ai = 0;
        if (!f32_in(va, 0, 80)) f_af = 0;
        if (!int_in(vb, 0, 80)) f_bi = 0;
        if (!f32_in(vb, 0, 80)) f_bf = 0;
    }
    #pragma unroll
    for (int k = 0; k < 4; k++) {
        int i = (t + 256*k) * (SEM_ELEMS/1024);
        unsigned int v = sem[i];
        if (!int_in(v, 0, NSEM)) f_si = 0;
        if (!f32_in(v, 0, NSEM)) f_sf = 0;
    }
    #pragma unroll
    for (int k = 0; k < 4; k++) {
        unsigned int v = masks[t + 256*k];
        if (!(v == 0u || v == 1u || v == 0x3F800000u)) f_w = 0;
    }
    __syncthreads();
    if (t == 0) {
        int a_cls = (f_ai | f_af);
        g_a_is_cls = a_cls;
        g_cls_f32  = a_cls ? (f_af && !f_ai) : (f_bf && !f_bi);
        g_sem_f32  = (f_sf && !f_si);
        g_mask_byte = f_w ? 0 : 1;
    }
}

// ---------------- stable descending sort of 100 scores per batch -----------
__global__ void k_sort(const unsigned int* __restrict__ pa,
                       const unsigned int* __restrict__ pb) {
    const unsigned int* scores = g_a_is_cls ? pb : pa;
    const unsigned int* cls    = g_a_is_cls ? pa : pb;
    int clsf = g_cls_f32;
    __shared__ float ss[BB][NN];
    int t = threadIdx.x;
    for (int i = t; i < BB*NN; i += blockDim.x)
        ss[i/NN][i%NN] = __uint_as_float(scores[i]);
    __syncthreads();
    for (int idx = t; idx < BB*NN; idx += blockDim.x) {
        int b = idx / NN, i = idx % NN;
        float si = ss[b][i];
        int r = 0;
        #pragma unroll 4
        for (int j = 0; j < NN; j++) {
            float sj = ss[b][j];
            r += (sj > si) || (sj == si && j < i);
        }
        unsigned int rawc = cls[b*NN + i];
        int c = clsf ? (int)__uint_as_float(rawc) : (int)rawc;
        g_order[b][r]  = i;
        g_sscore[b][r] = si;
        g_scls[b][r]   = c;
    }
}

// ---------------- pack: thread assembles its OWN word, zero shuffles --------
__global__ void k_pack(const unsigned int* __restrict__ masks) {
    int b = blockIdx.z, r = blockIdx.y;
    int t = threadIdx.x, lane = t & 31, wp = t >> 5;
    bool cand = (g_sscore[b][r] >= 0.5f);
    int orig = g_order[b][r];
    int w = blockIdx.x * 256 + t;
    bool valid = (w < WORDS);
    uint32_t word = 0;

    if (!g_mask_byte) {
        const uint4* mp = (const uint4*)(masks + (size_t)(b*NN + orig) * PP);
        if (cand && valid) {
            #pragma unroll
            for (int j = 0; j < 8; j++) {
                int q = blockIdx.x*2048 + wp*256 + j*32 + lane;  // coalesced
                uint4 x = mp[q];
                // wire-agnostic 0/1 test: works for int 1 and float 1.0f (bit23)
                uint32_t nib = ((x.x | (x.x >> 23)) & 1u)
                             | (((x.y | (x.y >> 23)) & 1u) << 1)
                             | (((x.z | (x.z >> 23)) & 1u) << 2)
                             | (((x.w | (x.w >> 23)) & 1u) << 3);
                word |= nib << (4*j);
            }
        }
    } else {
        const unsigned int* bp = (const unsigned int*)((const unsigned char*)masks
                                   + (size_t)(b*NN + orig) * PP);
        if (cand && valid) {
            #pragma unroll
            for (int j = 0; j < 8; j++) {
                int q = blockIdx.x*2048 + wp*256 + j*32 + lane;
                unsigned int v = bp[q];
                uint32_t nib = (v | (v >> 7) | (v >> 14) | (v >> 21)) & 0xFu;
                word |= nib << (4*j);
            }
        }
    }
    if (valid) g_planes[b][r][w] = word;

    int myarea = __popc(word);
    #pragma unroll
    for (int o = 16; o; o >>= 1) myarea += __shfl_down_sync(0xffffffffu, myarea, o);
    __shared__ int sa[TPB/32];
    if (lane == 0) sa[wp] = myarea;
    __syncthreads();
    if (t == 0) {
        int s = 0;
        #pragma unroll
        for (int k = 0; k < TPB/32; k++) s += sa[k];
        if (s) atomicAdd(&g_area[b][r], s);
    }
}

// ---------------- per-group phase (dead-group cutoff) ------------------------
__global__ void k_phase(int g) {
    int b = blockIdx.y;
    int t = threadIdx.x;
    int lane = t & 31, warp = t >> 5;
    int w = blockIdx.x * TPB + t;

    bool live = (g_sscore[b][g*G] >= 0.5f);
    int kmprev = (g > 0) ? g_keptmask[b][g-1] : 0;
    if (!live && kmprev == 0) return;

    uint32_t c = 0;
    if (w < WORDS) {
        c = g_claimed[b][w];
        if (kmprev) {
            int km = kmprev;
            int pbase = (g-1)*G;
            while (km) { int i = __ffs(km) - 1; km &= km - 1; c |= g_planes[b][pbase+i][w]; }
            g_claimed[b][w] = c;
        }
    }
    if (!live) return;

    __shared__ int s_hist[TPB/32][HSIZE];
    __shared__ int s_a[G];
    __shared__ unsigned s_old;
    for (int i = t; i < (TPB/32)*HSIZE; i += TPB) (&s_hist[0][0])[i] = 0;
    if (t < G) s_a[t] = 0;
    __syncthreads();

    int a_loc[G];
    #pragma unroll
    for (int i = 0; i < G; i++) a_loc[i] = 0;

    if (w < WORDS) {
        int base = g*G;
        uint32_t pw[G];
        #pragma unroll
        for (int i = 0; i < G; i++) pw[i] = g_planes[b][base+i][w];
        #pragma unroll
        for (int i = 0; i < G; i++) a_loc[i] = __popc(pw[i] & c);
        uint32_t u = ~c;
        while (u) {
            int p = __ffs(u) - 1; u &= u - 1;
            int pat = 0;
            #pragma unroll
            for (int i = 0; i < G; i++) pat |= (int)((pw[i] >> p) & 1u) << i;
            if (pat) atomicAdd(&s_hist[warp][pat], 1);
        }
    }
    #pragma unroll
    for (int i = 0; i < G; i++) {
        int v = a_loc[i];
        #pragma unroll
        for (int o = 16; o; o >>= 1) v += __shfl_down_sync(0xffffffffu, v, o);
        if (lane == 0 && v) atomicAdd(&s_a[i], v);
    }
    __syncthreads();
    for (int i = t; i < HSIZE; i += TPB) {
        int s = 0;
        #pragma unroll
        for (int k = 0; k < TPB/32; k++) s += s_hist[k][i];
        if (s) atomicAdd(&g_hist[b][g][i], s);
    }
    if (t < G && s_a[t]) atomicAdd(&g_interA[b][g][t], s_a[t]);
    __syncthreads();
    if (t == 0) {
        __threadfence();
        s_old = atomicAdd(&g_ticket[b][g], 1u);
    }
    __syncthreads();
    if (s_old != gridDim.x - 1) return;

    if (t >= 32) return;
    const int HL = HSIZE/32;
    int h[HL];
    #pragma unroll
    for (int k = 0; k < HL; k++) h[k] = __ldcg(&g_hist[b][g][lane*HL + k]);
    int keptm = 0;
    int iid = g_next_iid[b];
    int nk  = g_nkept[b];
    int base = g*G;
    for (int i = 0; i < G; i++) {
        int r = base + i;
        float s  = g_sscore[b][r];
        int area = __ldcg(&g_area[b][r]);
        int inter = __ldcg(&g_interA[b][g][i]);
        int loc = 0;
        #pragma unroll
        for (int k = 0; k < HL; k++) {
            int pat = lane*HL + k;
            if (((pat >> i) & 1) && (pat & keptm)) loc += h[k];
        }
        #pragma unroll
        for (int o = 16; o; o >>= 1) loc += __shfl_xor_sync(0xffffffffu, loc, o);
        inter += loc;
        bool keep = (s >= 0.5f) && (area > 0) && ((float)inter <= 0.5f * (float)area);
        if (keep) {
            if (lane == 0) {
                g_kept_rank[b][nk] = r;
                g_kept_val[b][nk]  = g_scls[b][r] + iid * 1000;
            }
            keptm |= 1 << i;
            iid++; nk++;
        }
    }
    if (lane == 0) {
        g_keptmask[b][g] = keptm;
        g_next_iid[b] = iid;
        g_nkept[b] = nk;
    }
}

// ---------------- stuff class histogram (thread owns its word) --------------
__global__ void k_stuff_hist(const unsigned int* __restrict__ sem) {
    int b = blockIdx.y;
    int t = threadIdx.x, lane = t & 31, wp = t >> 5;
    int semf = g_sem_f32;
    __shared__ int s_cnt[NSEM];
    for (int i = t; i < NSEM; i += TPB) s_cnt[i] = 0;

    int w = blockIdx.x * 256 + t;
    bool valid = (w < WORDS);
    uint32_t c = 0xFFFFFFFFu;
    if (valid) {
        c = g_claimed[b][w];
        int km = g_keptmask[b][NG-1];
        int pbase = (NG-1)*G;
        while (km) { int i = __ffs(km) - 1; km &= km - 1; c |= g_planes[b][pbase+i][w]; }
        g_claimed[b][w] = c;   // final claimed
    }
    __syncthreads();

    const uint4* sp4 = (const uint4*)(sem + (size_t)b*PP);
    if (valid && c != 0xFFFFFFFFu) {
        #pragma unroll
        for (int j = 0; j < 8; j++) {
            uint32_t nibc = (c >> (4*j)) & 0xFu;
            if (nibc != 0xFu) {
                int q = blockIdx.x*2048 + wp*256 + j*32 + lane;
                uint4 x = sp4[q];
                unsigned int vv[4] = {x.x, x.y, x.z, x.w};
                #pragma unroll
                for (int k = 0; k < 4; k++) {
                    if (!((nibc >> k) & 1u)) {
                        int s = semf ? (int)__uint_as_float(vv[k]) : (int)vv[k];
                        if (s >= 0 && s < NSEM) atomicAdd(&s_cnt[s], 1);
                    }
                }
            }
        }
    }
    __syncthreads();
    for (int i = t; i < NSEM; i += TPB)
        if (s_cnt[i]) atomicAdd(&g_cls_counts[b][i], s_cnt[i]);
}

// ---------------- final output write (float32-encoded) ----------------------
__global__ void k_final(const unsigned int* __restrict__ sem, uint4* __restrict__ out) {
    int b = blockIdx.y;
    int t = threadIdx.x, lane = t & 31, wp = t >> 5;
    int semf = g_sem_f32;
    __shared__ int s_kval[NN];
    __shared__ int s_krank[NN];
    __shared__ unsigned s_sval[NSEM];   // precomputed stuff value (float bits)
    int nk = g_nkept[b];
    if (t < nk) { s_kval[t] = g_kept_val[b][t]; s_krank[t] = g_kept_rank[b][t]; }
    for (int i = t; i < NSEM; i += TPB) {
        int v = (i < NSEM-1 && g_cls_counts[b][i] >= 4096) ? (i + 80) : 0;
        s_sval[i] = (unsigned int)__float_as_int((float)v);
    }
    __syncthreads();

    int w = blockIdx.x * 256 + t;
    if (w >= WORDS) return;
    uint32_t c = g_claimed[b][w];

    const uint4* sp4 = (const uint4*)(sem + (size_t)b*PP);
    uint4* op4 = out + (size_t)b*Q4S;
    #pragma unroll
    for (int j = 0; j < 8; j++) {
        int q = blockIdx.x*2048 + wp*256 + j*32 + lane;
        uint32_t nibc = (c >> (4*j)) & 0xFu;
        unsigned int vals[4];
        uint32_t rem = nibc;
        for (int k = 0; k < nk && rem; k++) {
            uint32_t pm = ((g_planes[b][s_krank[k]][w] >> (4*j)) & 0xFu) & rem;
            if (pm) {
                unsigned int fv = (unsigned int)__float_as_int((float)s_kval[k]);
                rem ^= pm;
                while (pm) { int p = __ffs(pm) - 1; pm &= pm - 1; vals[p] = fv; }
            }
        }
        uint32_t un = (~nibc) & 0xFu;
        if (un) {
            uint4 x = sp4[q];
            unsigned int vv[4] = {x.x, x.y, x.z, x.w};
            while (un) {
                int p = __ffs(un) - 1; un &= un - 1;
                int s = semf ? (int)__uint_as_float(vv[p]) : (int)vv[p];
                vals[p] = (s >= 0 && s < NSEM) ? s_sval[s]
                          : (unsigned int)__float_as_int(0.0f);
            }
        }
        op4[q] = make_uint4(vals[0], vals[1], vals[2], vals[3]);
    }
}

// ---------------- launch -----------------------------------------------------
extern "C" void kernel_launch(void* const* d_in, const int* in_sizes, int n_in,
                              void* d_out, int out_size) {
    const void* masks = nullptr;
    const void* sem   = nullptr;
    const void* smallA = nullptr;
    const void* smallB = nullptr;
    for (int i = 0; i < n_in; i++) {
        if (in_sizes[i] == MASK_ELEMS)      masks = d_in[i];
        else if (in_sizes[i] == SEM_ELEMS)  sem   = d_in[i];
        else if (in_sizes[i] == BB*NN) {
            if (!smallA) smallA = d_in[i]; else smallB = d_in[i];
        }
    }
    if (!masks)  masks  = d_in[0];
    if (!smallA) smallA = d_in[1];
    if (!smallB) smallB = d_in[2];
    if (!sem)    sem    = d_in[3];

    k_init<<<256, 256>>>();
    k_detect<<<1, 256>>>((const unsigned int*)smallA, (const unsigned int*)smallB,
                         (const unsigned int*)sem, (const unsigned int*)masks);
    k_sort<<<1, 256>>>((const unsigned int*)smallA, (const unsigned int*)smallB);
    k_pack<<<dim3(WBLK, NN, BB), TPB>>>((const unsigned int*)masks);
    for (int g = 0; g < NG; g++)
        k_phase<<<dim3(WBLK, BB), TPB>>>(g);
    k_stuff_hist<<<dim3(WBLK, BB), TPB>>>((const unsigned int*)sem);
    k_final<<<dim3(WBLK, BB), TPB>>>((const unsigned int*)sem, (uint4*)d_out);
}

// round 11
// speedup vs baseline: 1.6443x; 1.1603x over previous
#include <cuda_runtime.h>
#include <cstdint>
#include <cstddef>

#define BB 2
#define NN 100
#define HH 800
#define WW 1344
#define PP (HH*WW)          // 1075200 pixels per batch
#define WORDS (PP/32)       // 33600 words per plane
#define Q4S (PP/4)          // 268800 uint4 chunks per plane
#define G 10                // group size
#define NG (NN/G)           // 10 groups
#define HSIZE (1<<G)        // 1024 histogram buckets
#define NSEM 134
#define TPB 256
#define WBLK ((WORDS + TPB - 1)/TPB)   // 132

#define MASK_ELEMS (BB*NN*PP)
#define SEM_ELEMS  (BB*PP)

// Bit layout (permuted, consistent across ALL kernels):
//   word w = B*256 + wp*32 + lane   (B=block, wp=warp, lane)
//   bit (4j+k) of word w  <->  component k of uint4 q = B*2048 + wp*256 + j*32 + lane

// ---------------- device state ----------------------------------------------
__device__ uint32_t g_planes[BB][NN][WORDS];
__device__ int      g_order[BB][NN];
__device__ float    g_sscore[BB][NN];
__device__ int      g_scls[BB][NN];
__device__ int      g_area[BB][NN];
__device__ int      g_hist[BB][NG][HSIZE];
__device__ int      g_interA[BB][NG][G];
__device__ unsigned g_ticket[BB][NG+1];
__device__ int      g_flag[BB][NG+1];
__device__ int      g_keptmask[BB][NG];
__device__ int      g_nkept[BB];
__device__ int      g_kept_rank[BB][NN];
__device__ int      g_kept_val[BB][NN];
__device__ int      g_next_iid[BB];
__device__ int      g_cls_counts[BB][NSEM];
// transport flags
__device__ int      g_a_is_cls;
__device__ int      g_cls_f32;
__device__ int      g_sem_f32;
__device__ int      g_mask_byte;

// ---------------- init -------------------------------------------------------
__global__ void k_init() {
    int idx = blockIdx.x * blockDim.x + threadIdx.x;
    int stride = gridDim.x * blockDim.x;
    int* h = &g_hist[0][0][0];
    for (int i = idx; i < BB*NG*HSIZE; i += stride) h[i] = 0;
    int* ia = &g_interA[0][0][0];
    for (int i = idx; i < BB*NG*G; i += stride) ia[i] = 0;
    unsigned* tk = &g_ticket[0][0];
    int* fl = &g_flag[0][0];
    for (int i = idx; i < BB*(NG+1); i += stride) { tk[i] = 0u; fl[i] = 0; }
    int* km = &g_keptmask[0][0];
    for (int i = idx; i < BB*NG; i += stride) km[i] = 0;
    int* ar = &g_area[0][0];
    for (int i = idx; i < BB*NN; i += stride) ar[i] = 0;
    int* cc = &g_cls_counts[0][0];
    for (int i = idx; i < BB*NSEM; i += stride) cc[i] = 0;
    if (idx < BB) { g_nkept[idx] = 0; g_next_iid[idx] = 1; }
}

// ---------------- prep: transport detection + stable sort (one block) -------
__device__ __forceinline__ bool int_in(unsigned int raw, int lo, int hi) {
    int v = (int)raw; return v >= lo && v < hi;
}
__device__ __forceinline__ bool f32_in(unsigned int raw, int lo, int hi) {
    float f = __uint_as_float(raw);
    if (!(f >= (float)lo && f < (float)hi)) return false;
    return floorf(f) == f;
}

__global__ void k_prep(const unsigned int* __restrict__ pa,
                       const unsigned int* __restrict__ pb,
                       const unsigned int* __restrict__ sem,
                       const unsigned int* __restrict__ masks) {
    __shared__ int f_ai, f_af, f_bi, f_bf, f_si, f_sf, f_w;
    __shared__ float ss[BB][NN];
    int t = threadIdx.x;
    if (t == 0) { f_ai=1; f_af=1; f_bi=1; f_bf=1; f_si=1; f_sf=1; f_w=1; }
    __syncthreads();
    if (t < BB*NN) {
        unsigned int va = pa[t], vb = pb[t];
        if (!int_in(va, 0, 80)) f_ai = 0;
        if (!f32_in(va, 0, 80)) f_af = 0;
        if (!int_in(vb, 0, 80)) f_bi = 0;
        if (!f32_in(vb, 0, 80)) f_bf = 0;
    }
    #pragma unroll
    for (int k = 0; k < 4; k++) {
        int i = (t + 256*k) * (SEM_ELEMS/1024);
        unsigned int v = sem[i];
        if (!int_in(v, 0, NSEM)) f_si = 0;
        if (!f32_in(v, 0, NSEM)) f_sf = 0;
    }
    #pragma unroll
    for (int k = 0; k < 4; k++) {
        unsigned int v = masks[t + 256*k];
        if (!(v == 0u || v == 1u || v == 0x3F800000u)) f_w = 0;
    }
    __syncthreads();
    int a_cls = (f_ai | f_af);
    int clsf  = a_cls ? (f_af && !f_ai) : (f_bf && !f_bi);
    if (t == 0) {
        g_a_is_cls = a_cls;
        g_cls_f32  = clsf;
        g_sem_f32  = (f_sf && !f_si);
        g_mask_byte = f_w ? 0 : 1;
    }
    const unsigned int* scores = a_cls ? pb : pa;
    const unsigned int* cls    = a_cls ? pa : pb;
    for (int i = t; i < BB*NN; i += blockDim.x)
        ss[i/NN][i%NN] = __uint_as_float(scores[i]);
    __syncthreads();
    for (int idx = t; idx < BB*NN; idx += blockDim.x) {
        int b = idx / NN, i = idx % NN;
        float si = ss[b][i];
        int r = 0;
        #pragma unroll 4
        for (int j = 0; j < NN; j++) {
            float sj = ss[b][j];
            r += (sj > si) || (sj == si && j < i);
        }
        unsigned int rawc = cls[b*NN + i];
        int c = clsf ? (int)__uint_as_float(rawc) : (int)rawc;
        g_order[b][r]  = i;
        g_sscore[b][r] = si;
        g_scls[b][r]   = c;
    }
}

// ---------------- pack: thread assembles its OWN word, zero shuffles --------
__global__ void k_pack(const unsigned int* __restrict__ masks) {
    int b = blockIdx.z, r = blockIdx.y;
    int t = threadIdx.x, lane = t & 31, wp = t >> 5;
    bool cand = (g_sscore[b][r] >= 0.5f);
    int orig = g_order[b][r];
    int w = blockIdx.x * 256 + t;
    bool valid = (w < WORDS);
    uint32_t word = 0;

    if (!g_mask_byte) {
        const uint4* mp = (const uint4*)(masks + (size_t)(b*NN + orig) * PP);
        if (cand && valid) {
            #pragma unroll
            for (int j = 0; j < 8; j++) {
                int q = blockIdx.x*2048 + wp*256 + j*32 + lane;  // coalesced
                uint4 x = mp[q];
                // wire-agnostic 0/1 test: works for int 1 and float 1.0f (bit23)
                uint32_t nib = ((x.x | (x.x >> 23)) & 1u)
                             | (((x.y | (x.y >> 23)) & 1u) << 1)
                             | (((x.z | (x.z >> 23)) & 1u) << 2)
                             | (((x.w | (x.w >> 23)) & 1u) << 3);
                word |= nib << (4*j);
            }
        }
    } else {
        const unsigned int* bp = (const unsigned int*)((const unsigned char*)masks
                                   + (size_t)(b*NN + orig) * PP);
        if (cand && valid) {
            #pragma unroll
            for (int j = 0; j < 8; j++) {
                int q = blockIdx.x*2048 + wp*256 + j*32 + lane;
                unsigned int v = bp[q];
                uint32_t nib = (v | (v >> 7) | (v >> 14) | (v >> 21)) & 0xFu;
                word |= nib << (4*j);
            }
        }
    }
    if (valid) g_planes[b][r][w] = word;

    int myarea = __popc(word);
    #pragma unroll
    for (int o = 16; o; o >>= 1) myarea += __shfl_down_sync(0xffffffffu, myarea, o);
    __shared__ int sa[TPB/32];
    if (lane == 0) sa[wp] = myarea;
    __syncthreads();
    if (t == 0) {
        int s = 0;
        #pragma unroll
        for (int k = 0; k < TPB/32; k++) s += sa[k];
        if (s) atomicAdd(&g_area[b][r], s);
    }
}

// ---------------- fused: live phases + stuff hist + final write -------------
// Claimed mask is register-resident for the whole pipeline. Live groups are a
// prefix of the rank order (sorted by score), so `break` on first dead group.
__global__ void __launch_bounds__(TPB, 2)
k_run(const unsigned int* __restrict__ sem, uint4* __restrict__ out) {
    int b = blockIdx.y;
    int t = threadIdx.x, lane = t & 31, wp = t >> 5;
    int w = blockIdx.x * TPB + t;
    bool valid = (w < WORDS);
    uint32_t c = 0;                       // claimed word (register)

    __shared__ int s_hist[TPB/32][HSIZE]; // per-warp histograms (32KB)
    __shared__ int s_a[G];
    __shared__ unsigned s_old;
    __shared__ int s_km;
    __shared__ int s_nk;
    __shared__ int s_kr[NN];
    __shared__ int s_kv[NN];
    __shared__ unsigned s_sval[NSEM];
    int* s_cnt = &s_hist[0][0];           // alias (phases done before stuff)

    // ================= live phases =================
    for (int g = 0; g < NG; g++) {
        if (g_sscore[b][g*G] < 0.5f) break;     // dead prefix boundary

        for (int i = t; i < (TPB/32)*HSIZE; i += TPB) (&s_hist[0][0])[i] = 0;
        if (t < G) s_a[t] = 0;
        __syncthreads();

        uint32_t pw[G];
        #pragma unroll
        for (int i = 0; i < G; i++) pw[i] = valid ? g_planes[b][g*G+i][w] : 0u;

        int a_loc[G];
        #pragma unroll
        for (int i = 0; i < G; i++) a_loc[i] = __popc(pw[i] & c);

        uint32_t u = valid ? ~c : 0u;
        while (u) {
            int p = __ffs(u) - 1; u &= u - 1;
            int pat = 0;
            #pragma unroll
            for (int i = 0; i < G; i++) pat |= (int)((pw[i] >> p) & 1u) << i;
            if (pat) atomicAdd(&s_hist[wp][pat], 1);
        }
        #pragma unroll
        for (int i = 0; i < G; i++) {
            int v = a_loc[i];
            #pragma unroll
            for (int o = 16; o; o >>= 1) v += __shfl_down_sync(0xffffffffu, v, o);
            if (lane == 0 && v) atomicAdd(&s_a[i], v);
        }
        __syncthreads();
        for (int i = t; i < HSIZE; i += TPB) {
            int s = 0;
            #pragma unroll
            for (int k = 0; k < TPB/32; k++) s += s_hist[k][i];
            if (s) atomicAdd(&g_hist[b][g][i], s);
        }
        if (t < G && s_a[t]) atomicAdd(&g_interA[b][g][t], s_a[t]);
        __syncthreads();
        if (t == 0) {
            __threadfence();
            s_old = atomicAdd(&g_ticket[b][g], 1u);
        }
        __syncthreads();
        if (s_old == gridDim.x - 1) {
            if (wp == 0) {
                const int HL = HSIZE/32;
                int h[HL];
                #pragma unroll
                for (int k = 0; k < HL; k++) h[k] = __ldcg(&g_hist[b][g][lane*HL + k]);
                int keptm = 0;
                int iid = __ldcg(&g_next_iid[b]);
                int nk  = __ldcg(&g_nkept[b]);
                for (int i = 0; i < G; i++) {
                    int r = g*G + i;
                    float s  = g_sscore[b][r];
                    int area = __ldcg(&g_area[b][r]);
                    int inter = __ldcg(&g_interA[b][g][i]);
                    int loc = 0;
                    #pragma unroll
                    for (int k = 0; k < HL; k++) {
                        int pat = lane*HL + k;
                        if (((pat >> i) & 1) && (pat & keptm)) loc += h[k];
                    }
                    #pragma unroll
                    for (int o = 16; o; o >>= 1) loc += __shfl_xor_sync(0xffffffffu, loc, o);
                    inter += loc;
                    bool keep = (s >= 0.5f) && (area > 0) &&
                                ((float)inter <= 0.5f * (float)area);
                    if (keep) {
                        if (lane == 0) {
                            g_kept_rank[b][nk] = r;
                            g_kept_val[b][nk]  = g_scls[b][r] + iid * 1000;
                        }
                        keptm |= 1 << i;
                        iid++; nk++;
                    }
                }
                if (lane == 0) {
                    g_keptmask[b][g] = keptm;
                    g_next_iid[b] = iid;
                    g_nkept[b] = nk;
                    __threadfence();
                    atomicExch(&g_flag[b][g], 1);
                }
            }
            __syncthreads();
        }
        if (t == 0) {
            while (__ldcg(&g_flag[b][g]) == 0) __nanosleep(64);
            __threadfence();
            s_km = __ldcg(&g_keptmask[b][g]);
        }
        __syncthreads();
        int km = s_km;
        #pragma unroll
        for (int i = 0; i < G; i++)
            if ((km >> i) & 1) c |= pw[i];
        __syncthreads();       // protect s_hist reuse next iteration
    }

    // ================= stuff histogram (uses register claimed c) =============
    int semf = g_sem_f32;
    for (int i = t; i < NSEM; i += TPB) s_cnt[i] = 0;
    __syncthreads();
    const uint4* sp4 = (const uint4*)(sem + (size_t)b * PP);
    if (valid && c != 0xFFFFFFFFu) {
        #pragma unroll
        for (int j = 0; j < 8; j++) {
            uint32_t nibc = (c >> (4*j)) & 0xFu;
            if (nibc != 0xFu) {
                int q = blockIdx.x*2048 + wp*256 + j*32 + lane;
                uint4 x = sp4[q];
                unsigned int vv[4] = {x.x, x.y, x.z, x.w};
                #pragma unroll
                for (int k = 0; k < 4; k++) {
                    if (!((nibc >> k) & 1u)) {
                        int s = semf ? (int)__uint_as_float(vv[k]) : (int)vv[k];
                        if (s >= 0 && s < NSEM) atomicAdd(&s_cnt[s], 1);
                    }
                }
            }
        }
    }
    __syncthreads();
    for (int i = t; i < NSEM; i += TPB)
        if (s_cnt[i]) atomicAdd(&g_cls_counts[b][i], s_cnt[i]);

    // barrier: all counts in
    __threadfence();
    __syncthreads();
    if (t == 0) s_old = atomicAdd(&g_ticket[b][NG], 1u);
    __syncthreads();
    if (s_old == gridDim.x - 1) {
        if (t == 0) { __threadfence(); atomicExch(&g_flag[b][NG], 1); }
        __syncthreads();
    }
    if (t == 0) {
        while (__ldcg(&g_flag[b][NG]) == 0) __nanosleep(64);
        __threadfence();
        s_nk = __ldcg(&g_nkept[b]);
    }
    __syncthreads();
    int nk = s_nk;
    for (int i = t; i < NSEM; i += TPB) {
        int cnt = __ldcg(&g_cls_counts[b][i]);
        int v = (i < NSEM-1 && cnt >= 4096) ? (i + 80) : 0;
        s_sval[i] = (unsigned int)__float_as_int((float)v);
    }
    for (int i = t; i < nk; i += TPB) {
        s_kr[i] = __ldcg(&g_kept_rank[b][i]);
        s_kv[i] = __ldcg(&g_kept_val[b][i]);
    }
    __syncthreads();

    // ================= final write (float32-encoded output) ==================
    if (!valid) return;
    uint4* op4 = out + (size_t)b * Q4S;
    #pragma unroll
    for (int j = 0; j < 8; j++) {
        int q = blockIdx.x*2048 + wp*256 + j*32 + lane;
        uint32_t nibc = (c >> (4*j)) & 0xFu;
        unsigned int vals[4];
        uint32_t rem = nibc;
        for (int k = 0; k < nk && rem; k++) {
            uint32_t pm = ((g_planes[b][s_kr[k]][w] >> (4*j)) & 0xFu) & rem;
            if (pm) {
                unsigned int fv = (unsigned int)__float_as_int((float)s_kv[k]);
                rem ^= pm;
                while (pm) { int p = __ffs(pm) - 1; pm &= pm - 1; vals[p] = fv; }
            }
        }
        uint32_t un = (~nibc) & 0xFu;
        if (un) {
            uint4 x = sp4[q];
            unsigned int vv[4] = {x.x, x.y, x.z, x.w};
            while (un) {
                int p = __ffs(un) - 1; un &= un - 1;
                int s = semf ? (int)__uint_as_float(vv[p]) : (int)vv[p];
                vals[p] = (s >= 0 && s < NSEM) ? s_sval[s]
                          : (unsigned int)__float_as_int(0.0f);
            }
        }
        op4[q] = make_uint4(vals[0], vals[1], vals[2], vals[3]);
    }
}

// ---------------- launch -----------------------------------------------------
extern "C" void kernel_launch(void* const* d_in, const int* in_sizes, int n_in,
                              void* d_out, int out_size) {
    const void* masks = nullptr;
    const void* sem   = nullptr;
    const void* smallA = nullptr;
    const void* smallB = nullptr;
    for (int i = 0; i < n_in; i++) {
        if (in_sizes[i] == MASK_ELEMS)      masks = d_in[i];
        else if (in_sizes[i] == SEM_ELEMS)  sem   = d_in[i];
        else if (in_sizes[i] == BB*NN) {
            if (!smallA) smallA = d_in[i]; else smallB = d_in[i];
        }
    }
    if (!masks)  masks  = d_in[0];
    if (!smallA) smallA = d_in[1];
    if (!smallB) smallB = d_in[2];
    if (!sem)    sem    = d_in[3];

    k_init<<<128, 256>>>();
    k_prep<<<1, 256>>>((const unsigned int*)smallA, (const unsigned int*)smallB,
                       (const unsigned int*)sem, (const unsigned int*)masks);
    k_pack<<<dim3(WBLK, NN, BB), TPB>>>((const unsigned int*)masks);
    k_run<<<dim3(WBLK, BB), TPB>>>((const unsigned int*)sem, (uint4*)d_out);
}